// round 1
// baseline (speedup 1.0000x reference)
#include <cuda_runtime.h>
#include <math.h>

#define Bsz 4
#define Lsz 2048
#define Dsz 512
#define Hsz 8
#define Asz 64
#define Msz (Bsz*Lsz)   // 8192 rows

// ---------------- scratch (static device globals; no allocation) ----------------
__device__ float g_qcat[(size_t)Bsz*Hsz*Lsz*128];  // fused [B,H,L,128]: qd | qt
__device__ float g_kcat[(size_t)Bsz*Hsz*Lsz*128];  // fused [B,H,L,128]: kd | kt
__device__ float g_v   [(size_t)Bsz*Hsz*Lsz*Asz];  // [B,H,L,64]
__device__ float g_ctx [(size_t)Bsz*Hsz*Lsz*Asz];  // [B,H,L,64]
__device__ float g_x   [(size_t)Msz*Dsz];          // pre-LN activations

// ---------------- projection GEMM: [8192,512] x [512,512] + bias ----------------
// Output scattered into headed layout [B,H,L,CD] at column offset coff.
__global__ void proj_gemm(const float* __restrict__ X, const float* __restrict__ W,
                          const float* __restrict__ bias, float* __restrict__ out,
                          int CD, int coff)
{
    __shared__ float As[16][68];   // As[k][m], padded for float4 + banks
    __shared__ float Bs[16][64];   // Bs[k][n]
    const int tid = threadIdx.x;
    const int m0 = blockIdx.y * 64;
    const int n0 = blockIdx.x * 64;
    const int la_r = tid >> 2;
    const int la_c = (tid & 3) << 2;
    const int lb_r = tid >> 4;
    const int lb_c = (tid & 15) << 2;
    const int ty = tid >> 4, tx = tid & 15;
    float acc[4][4] = {};

    for (int k0 = 0; k0 < Dsz; k0 += 16) {
        float4 a = *reinterpret_cast<const float4*>(&X[(size_t)(m0 + la_r) * Dsz + k0 + la_c]);
        As[la_c+0][la_r] = a.x; As[la_c+1][la_r] = a.y;
        As[la_c+2][la_r] = a.z; As[la_c+3][la_r] = a.w;
        *reinterpret_cast<float4*>(&Bs[lb_r][lb_c]) =
            *reinterpret_cast<const float4*>(&W[(size_t)(k0 + lb_r) * Dsz + n0 + lb_c]);
        __syncthreads();
        #pragma unroll
        for (int k = 0; k < 16; k++) {
            float4 ra = *reinterpret_cast<const float4*>(&As[k][ty << 2]);
            float4 rb = *reinterpret_cast<const float4*>(&Bs[k][tx << 2]);
            float Ar[4] = {ra.x, ra.y, ra.z, ra.w};
            float Br[4] = {rb.x, rb.y, rb.z, rb.w};
            #pragma unroll
            for (int i = 0; i < 4; i++)
                #pragma unroll
                for (int j = 0; j < 4; j++)
                    acc[i][j] = fmaf(Ar[i], Br[j], acc[i][j]);
        }
        __syncthreads();
    }
    #pragma unroll
    for (int i = 0; i < 4; i++) {
        int m = m0 + (ty << 2) + i;
        int bb = m >> 11, l = m & (Lsz - 1);
        #pragma unroll
        for (int j = 0; j < 4; j++) {
            int n = n0 + (tx << 2) + j;
            int h = n >> 6, a = n & 63;
            out[((size_t)((bb*Hsz + h)*Lsz) + l) * (size_t)CD + coff + a] = acc[i][j] + bias[n];
        }
    }
}

// ---------------- output GEMM: gather ctx [B,H,L,64] -> x = ctx@Wo + bo + residual ----
__global__ void out_gemm(const float* __restrict__ CTX, const float* __restrict__ W,
                         const float* __restrict__ bias, const float* __restrict__ RES,
                         float* __restrict__ out)
{
    __shared__ float As[16][68];
    __shared__ float Bs[16][64];
    const int tid = threadIdx.x;
    const int m0 = blockIdx.y * 64;
    const int n0 = blockIdx.x * 64;
    const int la_r = tid >> 2;
    const int la_c = (tid & 3) << 2;
    const int lb_r = tid >> 4;
    const int lb_c = (tid & 15) << 2;
    const int ty = tid >> 4, tx = tid & 15;
    float acc[4][4] = {};

    const int mA = m0 + la_r;
    const int bbA = mA >> 11, lA = mA & (Lsz - 1);

    for (int k0 = 0; k0 < Dsz; k0 += 16) {
        int k = k0 + la_c;
        int h = k >> 6, a = k & 63;   // 4-span never crosses a 64 boundary (a%4==0)
        float4 av = *reinterpret_cast<const float4*>(
            &CTX[((size_t)((bbA*Hsz + h)*Lsz) + lA) * Asz + a]);
        As[la_c+0][la_r] = av.x; As[la_c+1][la_r] = av.y;
        As[la_c+2][la_r] = av.z; As[la_c+3][la_r] = av.w;
        *reinterpret_cast<float4*>(&Bs[lb_r][lb_c]) =
            *reinterpret_cast<const float4*>(&W[(size_t)(k0 + lb_r) * Dsz + n0 + lb_c]);
        __syncthreads();
        #pragma unroll
        for (int kk = 0; kk < 16; kk++) {
            float4 ra = *reinterpret_cast<const float4*>(&As[kk][ty << 2]);
            float4 rb = *reinterpret_cast<const float4*>(&Bs[kk][tx << 2]);
            float Ar[4] = {ra.x, ra.y, ra.z, ra.w};
            float Br[4] = {rb.x, rb.y, rb.z, rb.w};
            #pragma unroll
            for (int i = 0; i < 4; i++)
                #pragma unroll
                for (int j = 0; j < 4; j++)
                    acc[i][j] = fmaf(Ar[i], Br[j], acc[i][j]);
        }
        __syncthreads();
    }
    #pragma unroll
    for (int i = 0; i < 4; i++) {
        int m = m0 + (ty << 2) + i;
        #pragma unroll
        for (int j = 0; j < 4; j++) {
            int n = n0 + (tx << 2) + j;
            size_t idx = (size_t)m * Dsz + n;
            out[idx] = acc[i][j] + bias[n] + RES[idx];
        }
    }
}

// ---------------- flash attention: d_qk=128 (fused dual QK), d_v=64 ----------------
// grid = (L/64, B*H), 256 threads, online softmax. ~98KB dynamic smem.
#define ATTN_SMEM ((2*64*129 + 2*64*65 + 3*64) * 4)

__global__ void attn_kernel(const float* __restrict__ QC, const float* __restrict__ KC,
                            const float* __restrict__ V, float* __restrict__ CTX)
{
    extern __shared__ float sm[];
    float* qs   = sm;               // [64][129]
    float* ks   = qs + 64*129;      // [64][129]
    float* vs   = ks + 64*129;      // [64][65]
    float* Ss   = vs + 64*65;       // [64][65]
    float* rowm = Ss + 64*65;       // [64]
    float* rowl = rowm + 64;        // [64]
    float* corr = rowl + 64;        // [64]

    const int tid = threadIdx.x;
    const int ty = tid >> 4, tx = tid & 15;
    const int bh = blockIdx.y;
    const int q0 = blockIdx.x * 64;
    const size_t qbase = ((size_t)bh * Lsz + q0) * 128;

    for (int i = tid; i < 64*128; i += 256) {
        int r = i >> 7, c = i & 127;
        qs[r*129 + c] = QC[qbase + (size_t)r*128 + c];
    }
    if (tid < 64) { rowm[tid] = -3.0e38f; rowl[tid] = 0.0f; }

    float o[4][4] = {};

    for (int kt = 0; kt < Lsz/64; kt++) {
        const size_t kb = (size_t)bh * Lsz + kt*64;
        __syncthreads();   // also covers qs load + rowm/rowl init on first iter
        for (int i = tid; i < 64*128; i += 256) {
            int r = i >> 7, c = i & 127;
            ks[r*129 + c] = KC[(kb + r)*128 + c];
        }
        for (int i = tid; i < 64*64; i += 256) {
            int r = i >> 6, c = i & 63;
            vs[r*65 + c] = V[(kb + r)*64 + c];
        }
        __syncthreads();

        // S = q @ k^T over 128 dims (= qd.kd + qt.kt)
        float s[4][4] = {};
        #pragma unroll 4
        for (int k = 0; k < 128; k++) {
            float ra[4], rb[4];
            #pragma unroll
            for (int i = 0; i < 4; i++) ra[i] = qs[(ty*4+i)*129 + k];
            #pragma unroll
            for (int j = 0; j < 4; j++) rb[j] = ks[(tx*4+j)*129 + k];
            #pragma unroll
            for (int i = 0; i < 4; i++)
                #pragma unroll
                for (int j = 0; j < 4; j++)
                    s[i][j] = fmaf(ra[i], rb[j], s[i][j]);
        }
        #pragma unroll
        for (int i = 0; i < 4; i++)
            #pragma unroll
            for (int j = 0; j < 4; j++)
                Ss[(ty*4+i)*65 + tx*4+j] = s[i][j] * 0.125f;   // 1/sqrt(64)
        __syncthreads();

        // online softmax, one thread per row
        if (tid < 64) {
            float mloc = -3.0e38f;
            #pragma unroll 8
            for (int c = 0; c < 64; c++) mloc = fmaxf(mloc, Ss[tid*65 + c]);
            float mo = rowm[tid];
            float mn = fmaxf(mo, mloc);
            float cf = __expf(mo - mn);
            float sum = 0.0f;
            #pragma unroll 8
            for (int c = 0; c < 64; c++) {
                float p = __expf(Ss[tid*65 + c] - mn);
                Ss[tid*65 + c] = p;
                sum += p;
            }
            rowl[tid] = rowl[tid]*cf + sum;
            rowm[tid] = mn;
            corr[tid] = cf;
        }
        __syncthreads();

        // rescale O, accumulate O += P @ V
        float cfr[4];
        #pragma unroll
        for (int i = 0; i < 4; i++) cfr[i] = corr[ty*4+i];
        #pragma unroll
        for (int i = 0; i < 4; i++)
            #pragma unroll
            for (int j = 0; j < 4; j++)
                o[i][j] *= cfr[i];
        #pragma unroll 2
        for (int kk = 0; kk < 64; kk++) {
            float pa[4], vb[4];
            #pragma unroll
            for (int i = 0; i < 4; i++) pa[i] = Ss[(ty*4+i)*65 + kk];
            #pragma unroll
            for (int j = 0; j < 4; j++) vb[j] = vs[kk*65 + tx*4+j];
            #pragma unroll
            for (int i = 0; i < 4; i++)
                #pragma unroll
                for (int j = 0; j < 4; j++)
                    o[i][j] = fmaf(pa[i], vb[j], o[i][j]);
        }
    }
    __syncthreads();
    if (tid < 64) corr[tid] = 1.0f / rowl[tid];
    __syncthreads();
    #pragma unroll
    for (int i = 0; i < 4; i++) {
        int q = q0 + ty*4 + i;
        float inv = corr[ty*4+i];
        #pragma unroll
        for (int j = 0; j < 4; j++)
            CTX[((size_t)bh*Lsz + q)*Asz + tx*4 + j] = o[i][j] * inv;
    }
}

// ---------------- LayerNorm: one block per row ----------------
__global__ void ln_kernel(const float* __restrict__ X, const float* __restrict__ g,
                          const float* __restrict__ b, float* __restrict__ out)
{
    const int row = blockIdx.x;
    const float* xr = X + (size_t)row * Dsz;
    const int t = threadIdx.x;
    float v0 = xr[t];
    float v1 = xr[t + 256];
    float s  = v0 + v1;
    float s2 = v0*v0 + v1*v1;
    #pragma unroll
    for (int off = 16; off; off >>= 1) {
        s  += __shfl_down_sync(0xffffffffu, s,  off);
        s2 += __shfl_down_sync(0xffffffffu, s2, off);
    }
    __shared__ float ws[8], ws2[8];
    __shared__ float mu_s, rstd_s;
    int w = t >> 5, ln = t & 31;
    if (ln == 0) { ws[w] = s; ws2[w] = s2; }
    __syncthreads();
    if (t == 0) {
        float S = 0, S2 = 0;
        #pragma unroll
        for (int i = 0; i < 8; i++) { S += ws[i]; S2 += ws2[i]; }
        float mu  = S  * (1.0f / Dsz);
        float var = S2 * (1.0f / Dsz) - mu*mu;
        mu_s = mu;
        rstd_s = rsqrtf(var + 1e-5f);
    }
    __syncthreads();
    float mu = mu_s, rstd = rstd_s;
    out[(size_t)row*Dsz + t]       = (v0 - mu)*rstd*g[t]       + b[t];
    out[(size_t)row*Dsz + t + 256] = (v1 - mu)*rstd*g[t + 256] + b[t + 256];
}

// ---------------- launcher ----------------
extern "C" void kernel_launch(void* const* d_in, const int* in_sizes, int n_in,
                              void* d_out, int out_size)
{
    const float* Qd = (const float*)d_in[0];
    const float* Qt = (const float*)d_in[1];
    const float* Kd = (const float*)d_in[2];
    const float* Kt = (const float*)d_in[3];
    const float* Vt = (const float*)d_in[4];
    const float *Wqd, *Wqt, *Wkd, *Wkt, *Wvt, *Wo;
    const float *bqd, *bqt, *bkd, *bkt, *bvt, *bo;
    if (in_sizes[6] == Dsz) {
        // interleaved: w,b per projection (setup_inputs dict order)
        Wqd=(const float*)d_in[5];  bqd=(const float*)d_in[6];
        Wqt=(const float*)d_in[7];  bqt=(const float*)d_in[8];
        Wkd=(const float*)d_in[9];  bkd=(const float*)d_in[10];
        Wkt=(const float*)d_in[11]; bkt=(const float*)d_in[12];
        Wvt=(const float*)d_in[13]; bvt=(const float*)d_in[14];
        Wo =(const float*)d_in[15]; bo =(const float*)d_in[16];
    } else {
        // grouped: all weights then all biases (reference signature order)
        Wqd=(const float*)d_in[5];  Wqt=(const float*)d_in[6];
        Wkd=(const float*)d_in[7];  Wkt=(const float*)d_in[8];
        Wvt=(const float*)d_in[9];  Wo =(const float*)d_in[10];
        bqd=(const float*)d_in[11]; bqt=(const float*)d_in[12];
        bkd=(const float*)d_in[13]; bkt=(const float*)d_in[14];
        bvt=(const float*)d_in[15]; bo =(const float*)d_in[16];
    }
    const float* lg = (const float*)d_in[17];
    const float* lb = (const float*)d_in[18];

    float *qcat, *kcat, *vv, *ctx, *xx;
    cudaGetSymbolAddress((void**)&qcat, g_qcat);
    cudaGetSymbolAddress((void**)&kcat, g_kcat);
    cudaGetSymbolAddress((void**)&vv,   g_v);
    cudaGetSymbolAddress((void**)&ctx,  g_ctx);
    cudaGetSymbolAddress((void**)&xx,   g_x);

    cudaFuncSetAttribute((const void*)attn_kernel,
                         cudaFuncAttributeMaxDynamicSharedMemorySize, ATTN_SMEM);

    dim3 gg(Dsz/64, Msz/64);   // (8, 128)
    proj_gemm<<<gg, 256>>>(Qd, Wqd, bqd, qcat, 128, 0);
    proj_gemm<<<gg, 256>>>(Qt, Wqt, bqt, qcat, 128, 64);
    proj_gemm<<<gg, 256>>>(Kd, Wkd, bkd, kcat, 128, 0);
    proj_gemm<<<gg, 256>>>(Kt, Wkt, bkt, kcat, 128, 64);
    proj_gemm<<<gg, 256>>>(Vt, Wvt, bvt, vv, 64, 0);
    attn_kernel<<<dim3(Lsz/64, Bsz*Hsz), 256, ATTN_SMEM>>>(qcat, kcat, vv, ctx);
    out_gemm<<<gg, 256>>>(ctx, Wo, bo, Qd, xx);
    ln_kernel<<<Msz, 256>>>(xx, lg, lb, (float*)d_out);
}

// round 4
// speedup vs baseline: 7.7233x; 7.7233x over previous
#include <cuda_runtime.h>
#include <cuda_bf16.h>
#include <cstdint>
#include <cstdio>
#include <math.h>

typedef unsigned int u32;

#define Bsz 4
#define Lsz 2048
#define Dsz 512
#define Hsz 8
#define Asz 64
#define Msz (Bsz*Lsz)

// ================= scratch (POD types only; no class-type device globals) ======
__device__ unsigned short g_qcat[(size_t)Bsz*Hsz*Lsz*128];
__device__ unsigned short g_kcat[(size_t)Bsz*Hsz*Lsz*128];
__device__ unsigned short g_v[(size_t)Bsz*Hsz*Lsz*Asz];
__device__ unsigned short g_ctx[(size_t)Bsz*Hsz*Lsz*Asz];
__device__ float g_x[(size_t)Msz*Dsz];

// ================= helpers =================
__device__ __forceinline__ u32 sptr(const void* p)
{
    return (u32)__cvta_generic_to_shared(p);
}

__device__ __forceinline__ void ldmx4(u32* r, const void* p)
{
    asm volatile("ldmatrix.sync.aligned.m8n8.x4.shared.b16 {%0,%1,%2,%3}, [%4];"
                 : "=r"(r[0]), "=r"(r[1]), "=r"(r[2]), "=r"(r[3])
                 : "r"(sptr(p)));
}

__device__ __forceinline__ void ldmx4t(u32* r, const void* p)
{
    asm volatile("ldmatrix.sync.aligned.m8n8.x4.trans.shared.b16 {%0,%1,%2,%3}, [%4];"
                 : "=r"(r[0]), "=r"(r[1]), "=r"(r[2]), "=r"(r[3])
                 : "r"(sptr(p)));
}

__device__ __forceinline__ void mma_bf16(float* d, const u32* a, u32 b0, u32 b1)
{
    asm volatile(
        "mma.sync.aligned.m16n8k16.row.col.f32.bf16.bf16.f32 "
        "{%0,%1,%2,%3}, {%4,%5,%6,%7}, {%8,%9}, {%0,%1,%2,%3};"
        : "+f"(d[0]), "+f"(d[1]), "+f"(d[2]), "+f"(d[3])
        : "r"(a[0]), "r"(a[1]), "r"(a[2]), "r"(a[3]), "r"(b0), "r"(b1));
}

__device__ __forceinline__ u32 pk2(float lo, float hi)
{
    __nv_bfloat162 h = __floats2bfloat162_rn(lo, hi);
    return *reinterpret_cast<u32*>(&h);
}

// ================= projection GEMM (HMMA) =================
__global__ __launch_bounds__(256) void proj_mma(
    const float* __restrict__ X, const float* __restrict__ W,
    const float* __restrict__ bias, __nv_bfloat16* __restrict__ out,
    int CD, int coff)
{
    __shared__ __nv_bfloat16 As[128][40];
    __shared__ __nv_bfloat16 Bs[32][136];

    const int tid  = threadIdx.x;
    const int lane = tid & 31;
    const int wid  = tid >> 5;
    const int wm   = wid >> 2;
    const int wn   = wid & 3;
    const int m0   = blockIdx.y * 128;
    const int n0   = blockIdx.x * 128;
    const int lr   = tid >> 3;
    const int lc   = (tid & 7) * 4;
    float acc[4][4][4] = {};

    for (int k0 = 0; k0 < Dsz; k0 += 32) {
        float4 xa[4];
        float4 wa[4];
        #pragma unroll
        for (int i = 0; i < 4; i++) {
            xa[i] = *(const float4*)(X + (size_t)(m0 + lr + 32*i)*Dsz + k0 + lc);
        }
        #pragma unroll
        for (int i = 0; i < 4; i++) {
            wa[i] = *(const float4*)(W + (size_t)(k0 + lr)*Dsz + n0 + lc + 32*i);
        }
        __syncthreads();
        #pragma unroll
        for (int i = 0; i < 4; i++) {
            uint2 v;
            v.x = pk2(xa[i].x, xa[i].y);
            v.y = pk2(xa[i].z, xa[i].w);
            *(uint2*)(&As[lr + 32*i][lc]) = v;
        }
        #pragma unroll
        for (int i = 0; i < 4; i++) {
            uint2 v;
            v.x = pk2(wa[i].x, wa[i].y);
            v.y = pk2(wa[i].z, wa[i].w);
            *(uint2*)(&Bs[lr][lc + 32*i]) = v;
        }
        __syncthreads();
        #pragma unroll
        for (int ks = 0; ks < 32; ks += 16) {
            u32 af[4][4];
            u32 bfr[2][4];
            #pragma unroll
            for (int mt = 0; mt < 4; mt++) {
                ldmx4(af[mt], &As[wm*64 + mt*16 + (lane & 15)][ks + ((lane >> 4) << 3)]);
            }
            #pragma unroll
            for (int g = 0; g < 2; g++) {
                ldmx4t(bfr[g], &Bs[ks + (lane & 15)][wn*32 + g*16 + ((lane >> 4) << 3)]);
            }
            #pragma unroll
            for (int mt = 0; mt < 4; mt++) {
                #pragma unroll
                for (int nt = 0; nt < 4; nt++) {
                    mma_bf16(acc[mt][nt], af[mt],
                             bfr[nt >> 1][(nt & 1)*2], bfr[nt >> 1][(nt & 1)*2 + 1]);
                }
            }
        }
    }

    const int gid = lane >> 2;
    const int tig = lane & 3;
    #pragma unroll
    for (int mt = 0; mt < 4; mt++) {
        #pragma unroll
        for (int nt = 0; nt < 4; nt++) {
            int n = n0 + wn*32 + nt*8 + tig*2;
            float b0 = bias[n];
            float b1 = bias[n + 1];
            int h = n >> 6;
            int a = n & 63;
            #pragma unroll
            for (int rr = 0; rr < 2; rr++) {
                int m  = m0 + wm*64 + mt*16 + gid + rr*8;
                int bb = m >> 11;
                int l  = m & (Lsz - 1);
                __nv_bfloat162 o2 = __floats2bfloat162_rn(acc[mt][nt][rr*2] + b0,
                                                          acc[mt][nt][rr*2 + 1] + b1);
                *reinterpret_cast<__nv_bfloat162*>(
                    out + ((size_t)((bb*Hsz + h)*Lsz) + l)*CD + coff + a) = o2;
            }
        }
    }
}

// ================= output GEMM (HMMA) =================
__global__ __launch_bounds__(256) void out_mma(
    const __nv_bfloat16* __restrict__ CTX, const float* __restrict__ W,
    const float* __restrict__ bias, const float* __restrict__ RES,
    float* __restrict__ out)
{
    __shared__ __nv_bfloat16 As[128][40];
    __shared__ __nv_bfloat16 Bs[32][136];

    const int tid  = threadIdx.x;
    const int lane = tid & 31;
    const int wid  = tid >> 5;
    const int wm   = wid >> 2;
    const int wn   = wid & 3;
    const int m0   = blockIdx.y * 128;
    const int n0   = blockIdx.x * 128;
    const int lr   = tid >> 3;
    const int lc   = (tid & 7) * 4;
    float acc[4][4][4] = {};

    for (int k0 = 0; k0 < Dsz; k0 += 32) {
        uint4 av[2];
        float4 wa[4];
        #pragma unroll
        for (int i = 0; i < 2; i++) {
            int c   = tid + 256*i;
            int row = c >> 2;
            int kc  = (c & 3)*8;
            int m   = m0 + row;
            int bb  = m >> 11;
            int l   = m & (Lsz - 1);
            int kg  = k0 + kc;
            int h   = kg >> 6;
            int a   = kg & 63;
            av[i] = *(const uint4*)(CTX + ((size_t)((bb*Hsz + h)*Lsz) + l)*Asz + a);
        }
        #pragma unroll
        for (int i = 0; i < 4; i++) {
            wa[i] = *(const float4*)(W + (size_t)(k0 + lr)*Dsz + n0 + lc + 32*i);
        }
        __syncthreads();
        #pragma unroll
        for (int i = 0; i < 2; i++) {
            int c   = tid + 256*i;
            int row = c >> 2;
            int kc  = (c & 3)*8;
            *(uint4*)(&As[row][kc]) = av[i];
        }
        #pragma unroll
        for (int i = 0; i < 4; i++) {
            uint2 v;
            v.x = pk2(wa[i].x, wa[i].y);
            v.y = pk2(wa[i].z, wa[i].w);
            *(uint2*)(&Bs[lr][lc + 32*i]) = v;
        }
        __syncthreads();
        #pragma unroll
        for (int ks = 0; ks < 32; ks += 16) {
            u32 af[4][4];
            u32 bfr[2][4];
            #pragma unroll
            for (int mt = 0; mt < 4; mt++) {
                ldmx4(af[mt], &As[wm*64 + mt*16 + (lane & 15)][ks + ((lane >> 4) << 3)]);
            }
            #pragma unroll
            for (int g = 0; g < 2; g++) {
                ldmx4t(bfr[g], &Bs[ks + (lane & 15)][wn*32 + g*16 + ((lane >> 4) << 3)]);
            }
            #pragma unroll
            for (int mt = 0; mt < 4; mt++) {
                #pragma unroll
                for (int nt = 0; nt < 4; nt++) {
                    mma_bf16(acc[mt][nt], af[mt],
                             bfr[nt >> 1][(nt & 1)*2], bfr[nt >> 1][(nt & 1)*2 + 1]);
                }
            }
        }
    }

    const int gid = lane >> 2;
    const int tig = lane & 3;
    #pragma unroll
    for (int mt = 0; mt < 4; mt++) {
        #pragma unroll
        for (int nt = 0; nt < 4; nt++) {
            int n = n0 + wn*32 + nt*8 + tig*2;
            float b0 = bias[n];
            float b1 = bias[n + 1];
            #pragma unroll
            for (int rr = 0; rr < 2; rr++) {
                int m = m0 + wm*64 + mt*16 + gid + rr*8;
                size_t idx = (size_t)m*Dsz + n;
                float2 r2 = *(const float2*)(RES + idx);
                float2 o2;
                o2.x = acc[mt][nt][rr*2] + b0 + r2.x;
                o2.y = acc[mt][nt][rr*2 + 1] + b1 + r2.y;
                *(float2*)(out + idx) = o2;
            }
        }
    }
}

// ================= flash attention (HMMA) =================
__global__ __launch_bounds__(128) void attn_mma(
    const __nv_bfloat16* __restrict__ QC, const __nv_bfloat16* __restrict__ KC,
    const __nv_bfloat16* __restrict__ V, __nv_bfloat16* __restrict__ CTX)
{
    __shared__ __nv_bfloat16 Qs[64][136];
    __shared__ __nv_bfloat16 Ks[64][136];
    __shared__ __nv_bfloat16 Vs[64][72];

    const int tid  = threadIdx.x;
    const int lane = tid & 31;
    const int wid  = tid >> 5;
    const int gid  = lane >> 2;
    const int tig  = lane & 3;
    const int bh   = blockIdx.y;
    const int q0   = blockIdx.x * 64;

    const __nv_bfloat16* Qb = QC + ((size_t)bh*Lsz + q0)*128;
    #pragma unroll
    for (int i = 0; i < 8; i++) {
        int c  = tid + 128*i;
        int r  = c >> 4;
        int c8 = (c & 15)*8;
        *(uint4*)(&Qs[r][c8]) = *(const uint4*)(Qb + (size_t)r*128 + c8);
    }
    __syncthreads();

    u32 qf[8][4];
    #pragma unroll
    for (int ks = 0; ks < 8; ks++) {
        ldmx4(qf[ks], &Qs[wid*16 + (lane & 15)][ks*16 + ((lane >> 4) << 3)]);
    }

    float o[8][4] = {};
    float mr0 = -1e30f;
    float mr1 = -1e30f;
    float l0 = 0.0f;
    float l1 = 0.0f;

    for (int kt = 0; kt < Lsz/64; kt++) {
        const __nv_bfloat16* Kb = KC + ((size_t)bh*Lsz + kt*64)*128;
        const __nv_bfloat16* Vb = V + ((size_t)bh*Lsz + kt*64)*64;
        __syncthreads();
        #pragma unroll
        for (int i = 0; i < 8; i++) {
            int c  = tid + 128*i;
            int r  = c >> 4;
            int c8 = (c & 15)*8;
            *(uint4*)(&Ks[r][c8]) = *(const uint4*)(Kb + (size_t)r*128 + c8);
        }
        #pragma unroll
        for (int i = 0; i < 4; i++) {
            int c  = tid + 128*i;
            int r  = c >> 3;
            int c8 = (c & 7)*8;
            *(uint4*)(&Vs[r][c8]) = *(const uint4*)(Vb + (size_t)r*64 + c8);
        }
        __syncthreads();

        float s[8][4] = {};
        #pragma unroll
        for (int ks = 0; ks < 8; ks++) {
            u32 kb[4][4];
            #pragma unroll
            for (int g = 0; g < 4; g++) {
                ldmx4(kb[g], &Ks[g*16 + (lane & 15)][ks*16 + ((lane >> 4) << 3)]);
            }
            #pragma unroll
            for (int nt = 0; nt < 8; nt++) {
                int g   = nt >> 1;
                int odd = nt & 1;
                mma_bf16(s[nt], qf[ks], kb[g][odd], kb[g][odd + 2]);
            }
        }

        float mx0 = -1e30f;
        float mx1 = -1e30f;
        #pragma unroll
        for (int nt = 0; nt < 8; nt++) {
            #pragma unroll
            for (int j = 0; j < 4; j++) {
                s[nt][j] *= 0.125f;
            }
            mx0 = fmaxf(mx0, fmaxf(s[nt][0], s[nt][1]));
            mx1 = fmaxf(mx1, fmaxf(s[nt][2], s[nt][3]));
        }
        mx0 = fmaxf(mx0, __shfl_xor_sync(0xffffffffu, mx0, 1));
        mx0 = fmaxf(mx0, __shfl_xor_sync(0xffffffffu, mx0, 2));
        mx1 = fmaxf(mx1, __shfl_xor_sync(0xffffffffu, mx1, 1));
        mx1 = fmaxf(mx1, __shfl_xor_sync(0xffffffffu, mx1, 2));

        float mn0 = fmaxf(mr0, mx0);
        float mn1 = fmaxf(mr1, mx1);
        float cf0 = __expf(mr0 - mn0);
        float cf1 = __expf(mr1 - mn1);
        float sm0 = 0.0f;
        float sm1 = 0.0f;
        #pragma unroll
        for (int nt = 0; nt < 8; nt++) {
            s[nt][0] = __expf(s[nt][0] - mn0);
            s[nt][1] = __expf(s[nt][1] - mn0);
            s[nt][2] = __expf(s[nt][2] - mn1);
            s[nt][3] = __expf(s[nt][3] - mn1);
            sm0 += s[nt][0] + s[nt][1];
            sm1 += s[nt][2] + s[nt][3];
        }
        sm0 += __shfl_xor_sync(0xffffffffu, sm0, 1);
        sm0 += __shfl_xor_sync(0xffffffffu, sm0, 2);
        sm1 += __shfl_xor_sync(0xffffffffu, sm1, 1);
        sm1 += __shfl_xor_sync(0xffffffffu, sm1, 2);
        l0 = l0*cf0 + sm0;
        l1 = l1*cf1 + sm1;
        mr0 = mn0;
        mr1 = mn1;
        #pragma unroll
        for (int nt = 0; nt < 8; nt++) {
            o[nt][0] *= cf0;
            o[nt][1] *= cf0;
            o[nt][2] *= cf1;
            o[nt][3] *= cf1;
        }

        #pragma unroll
        for (int j = 0; j < 4; j++) {
            u32 pf[4];
            u32 vb[4][4];
            pf[0] = pk2(s[2*j][0], s[2*j][1]);
            pf[1] = pk2(s[2*j][2], s[2*j][3]);
            pf[2] = pk2(s[2*j + 1][0], s[2*j + 1][1]);
            pf[3] = pk2(s[2*j + 1][2], s[2*j + 1][3]);
            #pragma unroll
            for (int g = 0; g < 4; g++) {
                ldmx4t(vb[g], &Vs[j*16 + (lane & 15)][g*16 + ((lane >> 4) << 3)]);
            }
            #pragma unroll
            for (int nt = 0; nt < 8; nt++) {
                int g   = nt >> 1;
                int odd = (nt & 1)*2;
                mma_bf16(o[nt], pf, vb[g][odd], vb[g][odd + 1]);
            }
        }
    }

    float iv0 = 1.0f / l0;
    float iv1 = 1.0f / l1;
    int r0 = q0 + wid*16 + gid;
    #pragma unroll
    for (int nt = 0; nt < 8; nt++) {
        int cn = nt*8 + tig*2;
        *reinterpret_cast<__nv_bfloat162*>(CTX + ((size_t)bh*Lsz + r0)*Asz + cn) =
            __floats2bfloat162_rn(o[nt][0]*iv0, o[nt][1]*iv0);
        *reinterpret_cast<__nv_bfloat162*>(CTX + ((size_t)bh*Lsz + r0 + 8)*Asz + cn) =
            __floats2bfloat162_rn(o[nt][2]*iv1, o[nt][3]*iv1);
    }
}

// ================= LayerNorm =================
__global__ void ln_kernel(const float* __restrict__ X, const float* __restrict__ g,
                          const float* __restrict__ b, float* __restrict__ out)
{
    const int row = blockIdx.x;
    const float* xr = X + (size_t)row*Dsz;
    const int t = threadIdx.x;
    float v0 = xr[t];
    float v1 = xr[t + 256];
    float s1 = v0 + v1;
    float s2 = v0*v0 + v1*v1;
    #pragma unroll
    for (int off = 16; off; off >>= 1) {
        s1 += __shfl_down_sync(0xffffffffu, s1, off);
        s2 += __shfl_down_sync(0xffffffffu, s2, off);
    }
    __shared__ float ws[8];
    __shared__ float w2[8];
    __shared__ float mu_s;
    __shared__ float rs_s;
    int w = t >> 5;
    int ln = t & 31;
    if (ln == 0) {
        ws[w] = s1;
        w2[w] = s2;
    }
    __syncthreads();
    if (t == 0) {
        float S = 0.0f;
        float S2 = 0.0f;
        #pragma unroll
        for (int i = 0; i < 8; i++) {
            S += ws[i];
            S2 += w2[i];
        }
        float mu = S*(1.0f/Dsz);
        float var = S2*(1.0f/Dsz) - mu*mu;
        mu_s = mu;
        rs_s = rsqrtf(var + 1e-5f);
    }
    __syncthreads();
    float mu = mu_s;
    float rs = rs_s;
    out[(size_t)row*Dsz + t] = (v0 - mu)*rs*g[t] + b[t];
    out[(size_t)row*Dsz + t + 256] = (v1 - mu)*rs*g[t + 256] + b[t + 256];
}

// ================= launcher =================
extern "C" void kernel_launch(void* const* d_in, const int* in_sizes, int n_in,
                              void* d_out, int out_size)
{
    const float* Qd = (const float*)d_in[0];
    const float* Qt = (const float*)d_in[1];
    const float* Kd = (const float*)d_in[2];
    const float* Kt = (const float*)d_in[3];
    const float* Vt = (const float*)d_in[4];
    const float* Wqd;
    const float* Wqt;
    const float* Wkd;
    const float* Wkt;
    const float* Wvt;
    const float* Wo;
    const float* bqd;
    const float* bqt;
    const float* bkd;
    const float* bkt;
    const float* bvt;
    const float* bo;
    if (in_sizes[6] == Dsz) {
        Wqd = (const float*)d_in[5];
        bqd = (const float*)d_in[6];
        Wqt = (const float*)d_in[7];
        bqt = (const float*)d_in[8];
        Wkd = (const float*)d_in[9];
        bkd = (const float*)d_in[10];
        Wkt = (const float*)d_in[11];
        bkt = (const float*)d_in[12];
        Wvt = (const float*)d_in[13];
        bvt = (const float*)d_in[14];
        Wo  = (const float*)d_in[15];
        bo  = (const float*)d_in[16];
    } else {
        Wqd = (const float*)d_in[5];
        Wqt = (const float*)d_in[6];
        Wkd = (const float*)d_in[7];
        Wkt = (const float*)d_in[8];
        Wvt = (const float*)d_in[9];
        Wo  = (const float*)d_in[10];
        bqd = (const float*)d_in[11];
        bqt = (const float*)d_in[12];
        bkd = (const float*)d_in[13];
        bkt = (const float*)d_in[14];
        bvt = (const float*)d_in[15];
        bo  = (const float*)d_in[16];
    }
    const float* lg = (const float*)d_in[17];
    const float* lb = (const float*)d_in[18];

    void* p_qcat = 0;
    void* p_kcat = 0;
    void* p_v = 0;
    void* p_ctx = 0;
    void* p_x = 0;
    cudaGetSymbolAddress(&p_qcat, g_qcat);
    cudaGetSymbolAddress(&p_kcat, g_kcat);
    cudaGetSymbolAddress(&p_v, g_v);
    cudaGetSymbolAddress(&p_ctx, g_ctx);
    cudaGetSymbolAddress(&p_x, g_x);
    __nv_bfloat16* qcat = (__nv_bfloat16*)p_qcat;
    __nv_bfloat16* kcat = (__nv_bfloat16*)p_kcat;
    __nv_bfloat16* vv   = (__nv_bfloat16*)p_v;
    __nv_bfloat16* ctx  = (__nv_bfloat16*)p_ctx;
    float* xx = (float*)p_x;

    dim3 gp(Dsz/128, Msz/128);
    dim3 ga(Lsz/64, Bsz*Hsz);
    proj_mma<<<gp, 256>>>(Qd, Wqd, bqd, qcat, 128, 0);
    proj_mma<<<gp, 256>>>(Qt, Wqt, bqt, qcat, 128, 64);
    proj_mma<<<gp, 256>>>(Kd, Wkd, bkd, kcat, 128, 0);
    proj_mma<<<gp, 256>>>(Kt, Wkt, bkt, kcat, 128, 64);
    proj_mma<<<gp, 256>>>(Vt, Wvt, bvt, vv, 64, 0);
    attn_mma<<<ga, 128>>>(qcat, kcat, vv, ctx);
    out_mma<<<gp, 256>>>(ctx, Wo, bo, Qd, xx);
    ln_kernel<<<Msz, 256>>>(xx, lg, lb, (float*)d_out);
}

// round 6
// speedup vs baseline: 9.2073x; 1.1921x over previous
#include <cuda_runtime.h>
#include <cuda_bf16.h>
#include <cstdint>
#include <cstdio>
#include <math.h>

typedef unsigned int u32;

#define Bsz 4
#define Lsz 2048
#define Dsz 512
#define Hsz 8
#define Asz 64
#define Msz (Bsz*Lsz)
#define NKT (Lsz/64)

// ================= scratch =================
__device__ unsigned short g_qcat[(size_t)Bsz*Hsz*Lsz*128];
__device__ unsigned short g_kcat[(size_t)Bsz*Hsz*Lsz*128];
__device__ unsigned short g_v[(size_t)Bsz*Hsz*Lsz*Asz];
__device__ unsigned short g_ctx[(size_t)Bsz*Hsz*Lsz*Asz];
__device__ float g_x[(size_t)Msz*Dsz];

// ================= helpers =================
__device__ __forceinline__ u32 sptr(const void* p)
{
    return (u32)__cvta_generic_to_shared(p);
}

__device__ __forceinline__ void ldmx4(u32* r, const void* p)
{
    asm volatile("ldmatrix.sync.aligned.m8n8.x4.shared.b16 {%0,%1,%2,%3}, [%4];"
                 : "=r"(r[0]), "=r"(r[1]), "=r"(r[2]), "=r"(r[3])
                 : "r"(sptr(p)));
}

__device__ __forceinline__ void ldmx4t(u32* r, const void* p)
{
    asm volatile("ldmatrix.sync.aligned.m8n8.x4.trans.shared.b16 {%0,%1,%2,%3}, [%4];"
                 : "=r"(r[0]), "=r"(r[1]), "=r"(r[2]), "=r"(r[3])
                 : "r"(sptr(p)));
}

__device__ __forceinline__ void mma_bf16(float* d, const u32* a, u32 b0, u32 b1)
{
    asm volatile(
        "mma.sync.aligned.m16n8k16.row.col.f32.bf16.bf16.f32 "
        "{%0,%1,%2,%3}, {%4,%5,%6,%7}, {%8,%9}, {%0,%1,%2,%3};"
        : "+f"(d[0]), "+f"(d[1]), "+f"(d[2]), "+f"(d[3])
        : "r"(a[0]), "r"(a[1]), "r"(a[2]), "r"(a[3]), "r"(b0), "r"(b1));
}

__device__ __forceinline__ u32 pk2(float lo, float hi)
{
    __nv_bfloat162 h = __floats2bfloat162_rn(lo, hi);
    return *reinterpret_cast<u32*>(&h);
}

__device__ __forceinline__ void cpa16(u32 s, const void* g)
{
    asm volatile("cp.async.cg.shared.global [%0], [%1], 16;" :: "r"(s), "l"(g));
}

__device__ __forceinline__ void cpa_commit()
{
    asm volatile("cp.async.commit_group;");
}

// ================= fused projection GEMMs (HMMA, pipelined) =================
struct ProjOne {
    const float* X;
    const float* W;
    const float* Bv;
    __nv_bfloat16* out;
    int CD;
    int coff;
};
struct ProjAll {
    ProjOne p[5];
};

__global__ __launch_bounds__(256) void proj_mma(ProjAll args)
{
    __shared__ __nv_bfloat16 As[128][40];
    __shared__ __nv_bfloat16 Bs[32][136];

    const ProjOne pa = args.p[blockIdx.z];
    const float* __restrict__ X = pa.X;
    const float* __restrict__ W = pa.W;
    const float* __restrict__ bias = pa.Bv;
    __nv_bfloat16* __restrict__ out = pa.out;
    const int CD = pa.CD;
    const int coff = pa.coff;

    const int tid  = threadIdx.x;
    const int lane = tid & 31;
    const int wid  = tid >> 5;
    const int wm   = wid >> 2;
    const int wn   = wid & 3;
    const int m0   = blockIdx.y * 128;
    const int n0   = blockIdx.x * 128;
    const int lr   = tid >> 3;
    const int lc   = (tid & 7) * 4;
    float acc[4][4][4] = {};

    float4 xa[4];
    float4 wa[4];
    #pragma unroll
    for (int i = 0; i < 4; i++) {
        xa[i] = *(const float4*)(X + (size_t)(m0 + lr + 32*i)*Dsz + lc);
        wa[i] = *(const float4*)(W + (size_t)lr*Dsz + n0 + lc + 32*i);
    }

    for (int k0 = 0; k0 < Dsz; k0 += 32) {
        __syncthreads();
        #pragma unroll
        for (int i = 0; i < 4; i++) {
            uint2 v;
            v.x = pk2(xa[i].x, xa[i].y);
            v.y = pk2(xa[i].z, xa[i].w);
            *(uint2*)(&As[lr + 32*i][lc]) = v;
        }
        #pragma unroll
        for (int i = 0; i < 4; i++) {
            uint2 v;
            v.x = pk2(wa[i].x, wa[i].y);
            v.y = pk2(wa[i].z, wa[i].w);
            *(uint2*)(&Bs[lr][lc + 32*i]) = v;
        }
        __syncthreads();
        if (k0 + 32 < Dsz) {
            #pragma unroll
            for (int i = 0; i < 4; i++) {
                xa[i] = *(const float4*)(X + (size_t)(m0 + lr + 32*i)*Dsz + k0 + 32 + lc);
                wa[i] = *(const float4*)(W + (size_t)(k0 + 32 + lr)*Dsz + n0 + lc + 32*i);
            }
        }
        #pragma unroll
        for (int ks = 0; ks < 32; ks += 16) {
            u32 af[4][4];
            u32 bfr[2][4];
            #pragma unroll
            for (int mt = 0; mt < 4; mt++) {
                ldmx4(af[mt], &As[wm*64 + mt*16 + (lane & 15)][ks + ((lane >> 4) << 3)]);
            }
            #pragma unroll
            for (int g = 0; g < 2; g++) {
                ldmx4t(bfr[g], &Bs[ks + (lane & 15)][wn*32 + g*16 + ((lane >> 4) << 3)]);
            }
            #pragma unroll
            for (int mt = 0; mt < 4; mt++) {
                #pragma unroll
                for (int nt = 0; nt < 4; nt++) {
                    mma_bf16(acc[mt][nt], af[mt],
                             bfr[nt >> 1][(nt & 1)*2], bfr[nt >> 1][(nt & 1)*2 + 1]);
                }
            }
        }
    }

    const int gid = lane >> 2;
    const int tig = lane & 3;
    #pragma unroll
    for (int mt = 0; mt < 4; mt++) {
        #pragma unroll
        for (int nt = 0; nt < 4; nt++) {
            int n = n0 + wn*32 + nt*8 + tig*2;
            float b0 = bias[n];
            float b1 = bias[n + 1];
            int h = n >> 6;
            int a = n & 63;
            #pragma unroll
            for (int rr = 0; rr < 2; rr++) {
                int m  = m0 + wm*64 + mt*16 + gid + rr*8;
                int bb = m >> 11;
                int l  = m & (Lsz - 1);
                __nv_bfloat162 o2 = __floats2bfloat162_rn(acc[mt][nt][rr*2] + b0,
                                                          acc[mt][nt][rr*2 + 1] + b1);
                *reinterpret_cast<__nv_bfloat162*>(
                    out + ((size_t)((bb*Hsz + h)*Lsz) + l)*CD + coff + a) = o2;
            }
        }
    }
}

// ================= output GEMM (HMMA, pipelined) =================
__global__ __launch_bounds__(256) void out_mma(
    const __nv_bfloat16* __restrict__ CTX, const float* __restrict__ W,
    const float* __restrict__ bias, const float* __restrict__ RES,
    float* __restrict__ out)
{
    __shared__ __nv_bfloat16 As[128][40];
    __shared__ __nv_bfloat16 Bs[32][136];

    const int tid  = threadIdx.x;
    const int lane = tid & 31;
    const int wid  = tid >> 5;
    const int wm   = wid >> 2;
    const int wn   = wid & 3;
    const int m0   = blockIdx.y * 128;
    const int n0   = blockIdx.x * 128;
    const int lr   = tid >> 3;
    const int lc   = (tid & 7) * 4;
    float acc[4][4][4] = {};

    uint4 av[2];
    float4 wa[4];
    #pragma unroll
    for (int i = 0; i < 2; i++) {
        int c   = tid + 256*i;
        int row = c >> 2;
        int kc  = (c & 3)*8;
        int m   = m0 + row;
        int bb  = m >> 11;
        int l   = m & (Lsz - 1);
        int h   = kc >> 6;
        int a   = kc & 63;
        av[i] = *(const uint4*)(CTX + ((size_t)((bb*Hsz + h)*Lsz) + l)*Asz + a);
    }
    #pragma unroll
    for (int i = 0; i < 4; i++) {
        wa[i] = *(const float4*)(W + (size_t)lr*Dsz + n0 + lc + 32*i);
    }

    for (int k0 = 0; k0 < Dsz; k0 += 32) {
        __syncthreads();
        #pragma unroll
        for (int i = 0; i < 2; i++) {
            int c   = tid + 256*i;
            int row = c >> 2;
            int kc  = (c & 3)*8;
            *(uint4*)(&As[row][kc]) = av[i];
        }
        #pragma unroll
        for (int i = 0; i < 4; i++) {
            uint2 v;
            v.x = pk2(wa[i].x, wa[i].y);
            v.y = pk2(wa[i].z, wa[i].w);
            *(uint2*)(&Bs[lr][lc + 32*i]) = v;
        }
        __syncthreads();
        if (k0 + 32 < Dsz) {
            #pragma unroll
            for (int i = 0; i < 2; i++) {
                int c   = tid + 256*i;
                int row = c >> 2;
                int kc  = (c & 3)*8;
                int m   = m0 + row;
                int bb  = m >> 11;
                int l   = m & (Lsz - 1);
                int kg  = k0 + 32 + kc;
                int h   = kg >> 6;
                int a   = kg & 63;
                av[i] = *(const uint4*)(CTX + ((size_t)((bb*Hsz + h)*Lsz) + l)*Asz + a);
            }
            #pragma unroll
            for (int i = 0; i < 4; i++) {
                wa[i] = *(const float4*)(W + (size_t)(k0 + 32 + lr)*Dsz + n0 + lc + 32*i);
            }
        }
        #pragma unroll
        for (int ks = 0; ks < 32; ks += 16) {
            u32 af[4][4];
            u32 bfr[2][4];
            #pragma unroll
            for (int mt = 0; mt < 4; mt++) {
                ldmx4(af[mt], &As[wm*64 + mt*16 + (lane & 15)][ks + ((lane >> 4) << 3)]);
            }
            #pragma unroll
            for (int g = 0; g < 2; g++) {
                ldmx4t(bfr[g], &Bs[ks + (lane & 15)][wn*32 + g*16 + ((lane >> 4) << 3)]);
            }
            #pragma unroll
            for (int mt = 0; mt < 4; mt++) {
                #pragma unroll
                for (int nt = 0; nt < 4; nt++) {
                    mma_bf16(acc[mt][nt], af[mt],
                             bfr[nt >> 1][(nt & 1)*2], bfr[nt >> 1][(nt & 1)*2 + 1]);
                }
            }
        }
    }

    const int gid = lane >> 2;
    const int tig = lane & 3;
    #pragma unroll
    for (int mt = 0; mt < 4; mt++) {
        #pragma unroll
        for (int nt = 0; nt < 4; nt++) {
            int n = n0 + wn*32 + nt*8 + tig*2;
            float b0 = bias[n];
            float b1 = bias[n + 1];
            #pragma unroll
            for (int rr = 0; rr < 2; rr++) {
                int m = m0 + wm*64 + mt*16 + gid + rr*8;
                size_t idx = (size_t)m*Dsz + n;
                float2 r2 = *(const float2*)(RES + idx);
                float2 o2;
                o2.x = acc[mt][nt][rr*2] + b0 + r2.x;
                o2.y = acc[mt][nt][rr*2 + 1] + b1 + r2.y;
                *(float2*)(out + idx) = o2;
            }
        }
    }
}

// ================= flash attention (HMMA + cp.async double buffer) ===========
// dynamic smem: Qs[64][136] | Ks[2][64][136] | Vs[2][64][72]  (bf16)
#define ATTN_SMEM ((64*136 + 2*64*136 + 2*64*72) * 2)

__global__ __launch_bounds__(128) void attn_mma(
    const __nv_bfloat16* __restrict__ QC, const __nv_bfloat16* __restrict__ KC,
    const __nv_bfloat16* __restrict__ V, __nv_bfloat16* __restrict__ CTX)
{
    extern __shared__ __nv_bfloat16 dsm[];
    __nv_bfloat16* Qs = dsm;
    __nv_bfloat16* Ks = dsm + 64*136;
    __nv_bfloat16* Vs = dsm + 64*136 + 2*64*136;

    const int tid  = threadIdx.x;
    const int lane = tid & 31;
    const int wid  = tid >> 5;
    const int gid  = lane >> 2;
    const int tig  = lane & 3;
    const int bh   = blockIdx.y;
    const int q0   = blockIdx.x * 64;

    const __nv_bfloat16* Qb = QC + ((size_t)bh*Lsz + q0)*128;
    #pragma unroll
    for (int i = 0; i < 8; i++) {
        int c  = tid + 128*i;
        int r  = c >> 4;
        int c8 = (c & 15)*8;
        *(uint4*)(Qs + r*136 + c8) = *(const uint4*)(Qb + (size_t)r*128 + c8);
    }

    // prefetch tile 0 into buffer 0
    {
        const __nv_bfloat16* Kb = KC + (size_t)bh*Lsz*128;
        const __nv_bfloat16* Vb = V + (size_t)bh*Lsz*64;
        #pragma unroll
        for (int i = 0; i < 8; i++) {
            int c  = tid + 128*i;
            int r  = c >> 4;
            int c8 = (c & 15)*8;
            cpa16(sptr(Ks + r*136 + c8), Kb + (size_t)r*128 + c8);
        }
        #pragma unroll
        for (int i = 0; i < 4; i++) {
            int c  = tid + 128*i;
            int r  = c >> 3;
            int c8 = (c & 7)*8;
            cpa16(sptr(Vs + r*72 + c8), Vb + (size_t)r*64 + c8);
        }
        cpa_commit();
    }

    __syncthreads();
    u32 qf[8][4];
    #pragma unroll
    for (int ks = 0; ks < 8; ks++) {
        ldmx4(qf[ks], &Qs[(wid*16 + (lane & 15))*136 + ks*16 + ((lane >> 4) << 3)]);
    }

    float o[8][4] = {};
    float mr0 = -1e30f;
    float mr1 = -1e30f;
    float l0 = 0.0f;
    float l1 = 0.0f;

    for (int kt = 0; kt < NKT; kt++) {
        const int cur = kt & 1;
        if (kt + 1 < NKT) {
            const __nv_bfloat16* Kb = KC + ((size_t)bh*Lsz + (kt + 1)*64)*128;
            const __nv_bfloat16* Vb = V + ((size_t)bh*Lsz + (kt + 1)*64)*64;
            __nv_bfloat16* kd = Ks + (cur ^ 1)*64*136;
            __nv_bfloat16* vd = Vs + (cur ^ 1)*64*72;
            #pragma unroll
            for (int i = 0; i < 8; i++) {
                int c  = tid + 128*i;
                int r  = c >> 4;
                int c8 = (c & 15)*8;
                cpa16(sptr(kd + r*136 + c8), Kb + (size_t)r*128 + c8);
            }
            #pragma unroll
            for (int i = 0; i < 4; i++) {
                int c  = tid + 128*i;
                int r  = c >> 3;
                int c8 = (c & 7)*8;
                cpa16(sptr(vd + r*72 + c8), Vb + (size_t)r*64 + c8);
            }
            cpa_commit();
            asm volatile("cp.async.wait_group 1;");
        } else {
            asm volatile("cp.async.wait_group 0;");
        }
        __syncthreads();

        const __nv_bfloat16* kc = Ks + cur*64*136;
        const __nv_bfloat16* vc = Vs + cur*64*72;

        float s[8][4] = {};
        #pragma unroll
        for (int ks = 0; ks < 8; ks++) {
            u32 kb[4][4];
            #pragma unroll
            for (int g = 0; g < 4; g++) {
                ldmx4(kb[g], kc + (g*16 + (lane & 15))*136 + ks*16 + ((lane >> 4) << 3));
            }
            #pragma unroll
            for (int nt = 0; nt < 8; nt++) {
                int g   = nt >> 1;
                int odd = nt & 1;
                mma_bf16(s[nt], qf[ks], kb[g][odd], kb[g][odd + 2]);
            }
        }

        float mx0 = -1e30f;
        float mx1 = -1e30f;
        #pragma unroll
        for (int nt = 0; nt < 8; nt++) {
            #pragma unroll
            for (int j = 0; j < 4; j++) {
                s[nt][j] *= 0.125f;
            }
            mx0 = fmaxf(mx0, fmaxf(s[nt][0], s[nt][1]));
            mx1 = fmaxf(mx1, fmaxf(s[nt][2], s[nt][3]));
        }
        mx0 = fmaxf(mx0, __shfl_xor_sync(0xffffffffu, mx0, 1));
        mx0 = fmaxf(mx0, __shfl_xor_sync(0xffffffffu, mx0, 2));
        mx1 = fmaxf(mx1, __shfl_xor_sync(0xffffffffu, mx1, 1));
        mx1 = fmaxf(mx1, __shfl_xor_sync(0xffffffffu, mx1, 2));

        float mn0 = fmaxf(mr0, mx0);
        float mn1 = fmaxf(mr1, mx1);
        float cf0 = __expf(mr0 - mn0);
        float cf1 = __expf(mr1 - mn1);
        float sm0 = 0.0f;
        float sm1 = 0.0f;
        #pragma unroll
        for (int nt = 0; nt < 8; nt++) {
            s[nt][0] = __expf(s[nt][0] - mn0);
            s[nt][1] = __expf(s[nt][1] - mn0);
            s[nt][2] = __expf(s[nt][2] - mn1);
            s[nt][3] = __expf(s[nt][3] - mn1);
            sm0 += s[nt][0] + s[nt][1];
            sm1 += s[nt][2] + s[nt][3];
        }
        sm0 += __shfl_xor_sync(0xffffffffu, sm0, 1);
        sm0 += __shfl_xor_sync(0xffffffffu, sm0, 2);
        sm1 += __shfl_xor_sync(0xffffffffu, sm1, 1);
        sm1 += __shfl_xor_sync(0xffffffffu, sm1, 2);
        l0 = l0*cf0 + sm0;
        l1 = l1*cf1 + sm1;
        mr0 = mn0;
        mr1 = mn1;
        #pragma unroll
        for (int nt = 0; nt < 8; nt++) {
            o[nt][0] *= cf0;
            o[nt][1] *= cf0;
            o[nt][2] *= cf1;
            o[nt][3] *= cf1;
        }

        #pragma unroll
        for (int j = 0; j < 4; j++) {
            u32 pf[4];
            u32 vb[4][4];
            pf[0] = pk2(s[2*j][0], s[2*j][1]);
            pf[1] = pk2(s[2*j][2], s[2*j][3]);
            pf[2] = pk2(s[2*j + 1][0], s[2*j + 1][1]);
            pf[3] = pk2(s[2*j + 1][2], s[2*j + 1][3]);
            #pragma unroll
            for (int g = 0; g < 4; g++) {
                ldmx4t(vb[g], vc + (j*16 + (lane & 15))*72 + g*16 + ((lane >> 4) << 3));
            }
            #pragma unroll
            for (int nt = 0; nt < 8; nt++) {
                int g   = nt >> 1;
                int odd = (nt & 1)*2;
                mma_bf16(o[nt], pf, vb[g][odd], vb[g][odd + 1]);
            }
        }
        __syncthreads();
    }

    float iv0 = 1.0f / l0;
    float iv1 = 1.0f / l1;
    int r0 = q0 + wid*16 + gid;
    #pragma unroll
    for (int nt = 0; nt < 8; nt++) {
        int cn = nt*8 + tig*2;
        *reinterpret_cast<__nv_bfloat162*>(CTX + ((size_t)bh*Lsz + r0)*Asz + cn) =
            __floats2bfloat162_rn(o[nt][0]*iv0, o[nt][1]*iv0);
        *reinterpret_cast<__nv_bfloat162*>(CTX + ((size_t)bh*Lsz + r0 + 8)*Asz + cn) =
            __floats2bfloat162_rn(o[nt][2]*iv1, o[nt][3]*iv1);
    }
}

// ================= LayerNorm =================
__global__ void ln_kernel(const float* __restrict__ X, const float* __restrict__ g,
                          const float* __restrict__ b, float* __restrict__ out)
{
    const int row = blockIdx.x;
    const float* xr = X + (size_t)row*Dsz;
    const int t = threadIdx.x;
    float v0 = xr[t];
    float v1 = xr[t + 256];
    float s1 = v0 + v1;
    float s2 = v0*v0 + v1*v1;
    #pragma unroll
    for (int off = 16; off; off >>= 1) {
        s1 += __shfl_down_sync(0xffffffffu, s1, off);
        s2 += __shfl_down_sync(0xffffffffu, s2, off);
    }
    __shared__ float ws[8];
    __shared__ float w2[8];
    __shared__ float mu_s;
    __shared__ float rs_s;
    int w = t >> 5;
    int ln = t & 31;
    if (ln == 0) {
        ws[w] = s1;
        w2[w] = s2;
    }
    __syncthreads();
    if (t == 0) {
        float S = 0.0f;
        float S2 = 0.0f;
        #pragma unroll
        for (int i = 0; i < 8; i++) {
            S += ws[i];
            S2 += w2[i];
        }
        float mu = S*(1.0f/Dsz);
        float var = S2*(1.0f/Dsz) - mu*mu;
        mu_s = mu;
        rs_s = rsqrtf(var + 1e-5f);
    }
    __syncthreads();
    float mu = mu_s;
    float rs = rs_s;
    out[(size_t)row*Dsz + t] = (v0 - mu)*rs*g[t] + b[t];
    out[(size_t)row*Dsz + t + 256] = (v1 - mu)*rs*g[t + 256] + b[t + 256];
}

// ================= launcher =================
extern "C" void kernel_launch(void* const* d_in, const int* in_sizes, int n_in,
                              void* d_out, int out_size)
{
    const float* Qd = (const float*)d_in[0];
    const float* Qt = (const float*)d_in[1];
    const float* Kd = (const float*)d_in[2];
    const float* Kt = (const float*)d_in[3];
    const float* Vt = (const float*)d_in[4];
    const float* Wqd;
    const float* Wqt;
    const float* Wkd;
    const float* Wkt;
    const float* Wvt;
    const float* Wo;
    const float* bqd;
    const float* bqt;
    const float* bkd;
    const float* bkt;
    const float* bvt;
    const float* bo;
    if (in_sizes[6] == Dsz) {
        Wqd = (const float*)d_in[5];
        bqd = (const float*)d_in[6];
        Wqt = (const float*)d_in[7];
        bqt = (const float*)d_in[8];
        Wkd = (const float*)d_in[9];
        bkd = (const float*)d_in[10];
        Wkt = (const float*)d_in[11];
        bkt = (const float*)d_in[12];
        Wvt = (const float*)d_in[13];
        bvt = (const float*)d_in[14];
        Wo  = (const float*)d_in[15];
        bo  = (const float*)d_in[16];
    } else {
        Wqd = (const float*)d_in[5];
        Wqt = (const float*)d_in[6];
        Wkd = (const float*)d_in[7];
        Wkt = (const float*)d_in[8];
        Wvt = (const float*)d_in[9];
        Wo  = (const float*)d_in[10];
        bqd = (const float*)d_in[11];
        bqt = (const float*)d_in[12];
        bkd = (const float*)d_in[13];
        bkt = (const float*)d_in[14];
        bvt = (const float*)d_in[15];
        bo  = (const float*)d_in[16];
    }
    const float* lg = (const float*)d_in[17];
    const float* lb = (const float*)d_in[18];

    void* p_qcat = 0;
    void* p_kcat = 0;
    void* p_v = 0;
    void* p_ctx = 0;
    void* p_x = 0;
    cudaGetSymbolAddress(&p_qcat, g_qcat);
    cudaGetSymbolAddress(&p_kcat, g_kcat);
    cudaGetSymbolAddress(&p_v, g_v);
    cudaGetSymbolAddress(&p_ctx, g_ctx);
    cudaGetSymbolAddress(&p_x, g_x);
    __nv_bfloat16* qcat = (__nv_bfloat16*)p_qcat;
    __nv_bfloat16* kcat = (__nv_bfloat16*)p_kcat;
    __nv_bfloat16* vv   = (__nv_bfloat16*)p_v;
    __nv_bfloat16* ctx  = (__nv_bfloat16*)p_ctx;
    float* xx = (float*)p_x;

    static int smem_set = 0;
    if (!smem_set) {
        cudaFuncSetAttribute(attn_mma,
                             cudaFuncAttributeMaxDynamicSharedMemorySize, ATTN_SMEM);
        smem_set = 1;
    }

    ProjAll pj;
    pj.p[0].X = Qd;  pj.p[0].W = Wqd; pj.p[0].Bv = bqd; pj.p[0].out = qcat; pj.p[0].CD = 128; pj.p[0].coff = 0;
    pj.p[1].X = Qt;  pj.p[1].W = Wqt; pj.p[1].Bv = bqt; pj.p[1].out = qcat; pj.p[1].CD = 128; pj.p[1].coff = 64;
    pj.p[2].X = Kd;  pj.p[2].W = Wkd; pj.p[2].Bv = bkd; pj.p[2].out = kcat; pj.p[2].CD = 128; pj.p[2].coff = 0;
    pj.p[3].X = Kt;  pj.p[3].W = Wkt; pj.p[3].Bv = bkt; pj.p[3].out = kcat; pj.p[3].CD = 128; pj.p[3].coff = 64;
    pj.p[4].X = Vt;  pj.p[4].W = Wvt; pj.p[4].Bv = bvt; pj.p[4].out = vv;   pj.p[4].CD = 64;  pj.p[4].coff = 0;

    dim3 gp(Dsz/128, Msz/128, 5);
    dim3 go(Dsz/128, Msz/128);
    dim3 ga(Lsz/64, Bsz*Hsz);
    proj_mma<<<gp, 256>>>(pj);
    attn_mma<<<ga, 128, ATTN_SMEM>>>(qcat, kcat, vv, ctx);
    out_mma<<<go, 256>>>(ctx, Wo, bo, Qd, xx);
    ln_kernel<<<Msz, 256>>>(xx, lg, lb, (float*)d_out);
}